// round 16
// baseline (speedup 1.0000x reference)
#include <cuda_runtime.h>

// RX2: apply RX(theta_q) to each of 20 qubits of [16, 2^20] states.
// Stage k pairs amplitudes at stride 2^k and uses qubit 19-k.
//
// Packed (re,im) in 64-bit values, sm_103a f32x2 FMA: 4 fma-pipe instrs
// per butterfly. BIGGEST-kernel strategy (per-kernel fixed overhead ~7us
// dominates; R5-gen 512-thread/8192-amp bodies measured 3.0us/batch vs
// 4.25+ for smaller variants):
//   Pass 1: stages 0..12  (contiguous 8192-amp tiles, 3 smem exchanges,
//           stage 0 specialized for real input)
//   Pass 2: stages 13..19 (128 strided rows x 64 contiguous, 1 exchange)
// 2 groups of 8 batches on the 2 proven forked streams -> only 4 kernels;
// the two streams run symmetric p1||p1 then p2||p2 with 3 CTAs/SM mixed.

#define NQ 20
typedef unsigned long long u64;

__device__ __forceinline__ u64 pk2(float x, float y) {
    u64 v; asm("mov.b64 %0, {%1, %2};" : "=l"(v) : "f"(x), "f"(y)); return v;
}
__device__ __forceinline__ u64 swp(u64 v) {
    float x, y;
    asm("mov.b64 {%0, %1}, %2;" : "=f"(x), "=f"(y) : "l"(v));
    return pk2(y, x);
}
__device__ __forceinline__ u64 fma2(u64 a, u64 b, u64 c) {
    u64 d; asm("fma.rn.f32x2 %0, %1, %2, %3;" : "=l"(d) : "l"(a), "l"(b), "l"(c)); return d;
}
__device__ __forceinline__ u64 mul2(u64 a, u64 b) {
    u64 d; asm("mul.rn.f32x2 %0, %1, %2;" : "=l"(d) : "l"(a), "l"(b)); return d;
}

// a=(ar,ai), b=(br,bi); c2=(c,c), s2=(s,-s)
// na = c2*a + s2*swap(b) ; nb = c2*b + s2*swap(a)
__device__ __forceinline__ void bfly2(u64& a, u64& b, u64 c2, u64 s2) {
    u64 na = fma2(c2, a, mul2(s2, swp(b)));
    u64 nb = fma2(c2, b, mul2(s2, swp(a)));
    a = na; b = nb;
}

// -------------------------------------------------------------------------
// Pass 1: stages 0..12 (qubits 19..7). Tile = 8192 contiguous amplitudes.
// 512 threads, 16 amps/thread. Rounds: bits 0-3 / 4-7 / 8-11; final stage
// (bit 12) fused with the global store. Pad p = i + (i>>4).
// -------------------------------------------------------------------------
__global__ __launch_bounds__(512, 2)
void rx_pass1(const float* __restrict__ phi,
              const float* __restrict__ thetas,
              u64* __restrict__ out, int b0)
{
    extern __shared__ u64 sm[];              // 8704 u64
    __shared__ u64 c2B[13], s2B[13];
    __shared__ u64 cs0;                      // (c0, -s0) for real stage 0

    const int t    = threadIdx.x;
    const int b    = b0 + blockIdx.y;
    const int tile = blockIdx.x;
    const size_t base = ((size_t)b << 20) + ((size_t)tile << 13);

    if (t < 13) {
        float sv, cv;
        sincosf(0.5f * thetas[b * NQ + (19 - t)], &sv, &cv);
        c2B[t] = pk2(cv, cv);
        s2B[t] = pk2(sv, -sv);
        if (t == 0) cs0 = pk2(cv, -sv);
    }

    u64 amp[16];
    float rr[16];

    // ---- Round A: load real input (read-once: evict-first), idx = 16*t+j ----
    const float4* pin = (const float4*)(phi + base + ((size_t)t << 4));
    #pragma unroll
    for (int q = 0; q < 4; q++) {
        float4 v = __ldcs(pin + q);
        rr[4*q+0] = v.x; rr[4*q+1] = v.y; rr[4*q+2] = v.z; rr[4*q+3] = v.w;
    }
    __syncthreads();   // c2B/s2B visible

    // Stage 0 on real data: na = (c*ar, -s*br), nb = (c*br, -s*ar).
    {
        const u64 cs = cs0;
        #pragma unroll
        for (int j = 0; j < 16; j += 2) {
            amp[j]     = mul2(cs, pk2(rr[j],     rr[j + 1]));
            amp[j + 1] = mul2(cs, pk2(rr[j + 1], rr[j]));
        }
    }
    #pragma unroll
    for (int k = 1; k < 4; k++) {
        const u64 c2 = c2B[k], s2 = s2B[k];
        const int m = 1 << k;
        #pragma unroll
        for (int j = 0; j < 16; j++)
            if (!(j & m)) bfly2(amp[j], amp[j | m], c2, s2);
    }
    #pragma unroll
    for (int j = 0; j < 16; j++) {
        int i = (t << 4) + j;
        sm[i + (i >> 4)] = amp[j];
    }
    __syncthreads();

    // ---- Round B: idx = (t&15) | (j<<4) | ((t>>4)<<8) ----
    #pragma unroll
    for (int j = 0; j < 16; j++) {
        int i = (t & 15) | (j << 4) | ((t >> 4) << 8);
        amp[j] = sm[i + (i >> 4)];
    }
    #pragma unroll
    for (int k = 4; k < 8; k++) {
        const u64 c2 = c2B[k], s2 = s2B[k];
        const int m = 1 << (k - 4);
        #pragma unroll
        for (int j = 0; j < 16; j++)
            if (!(j & m)) bfly2(amp[j], amp[j | m], c2, s2);
    }
    __syncthreads();
    #pragma unroll
    for (int j = 0; j < 16; j++) {
        int i = (t & 15) | (j << 4) | ((t >> 4) << 8);
        sm[i + (i >> 4)] = amp[j];
    }
    __syncthreads();

    // ---- Round C: idx = (t&255) | (j<<8) | ((t>>8)<<12) ----
    #pragma unroll
    for (int j = 0; j < 16; j++) {
        int i = (t & 255) | (j << 8) | ((t >> 8) << 12);
        amp[j] = sm[i + (i >> 4)];
    }
    #pragma unroll
    for (int k = 8; k < 12; k++) {
        const u64 c2 = c2B[k], s2 = s2B[k];
        const int m = 1 << (k - 8);
        #pragma unroll
        for (int j = 0; j < 16; j++)
            if (!(j & m)) bfly2(amp[j], amp[j | m], c2, s2);
    }
    __syncthreads();
    #pragma unroll
    for (int j = 0; j < 16; j++) {
        int i = (t & 255) | (j << 8) | ((t >> 8) << 12);
        sm[i + (i >> 4)] = amp[j];
    }
    __syncthreads();

    // ---- Final stage: bit 12, fused with coalesced b64 store (stays in L2
    //      for pass2) ----
    {
        u64* po = out + base;
        const u64 c2 = c2B[12], s2 = s2B[12];
        #pragma unroll
        for (int jj = 0; jj < 8; jj++) {
            int p  = (jj << 9) + t;          // 0..4095, warp-consecutive
            int pb = p + 4096;
            u64 a  = sm[p  + (p  >> 4)];
            u64 bb = sm[pb + (pb >> 4)];
            bfly2(a, bb, c2, s2);
            po[p]  = a;
            po[pb] = bb;
        }
    }
}

// -------------------------------------------------------------------------
// Pass 2: stages 13..19 (qubits 6..0), in place on out.
// Tile: h = 0..127 (bits 13..19) x 64 contiguous. 512 threads, 16 amps,
// one smem exchange. Loads .cs (read-once), stores .cs (never re-read).
// -------------------------------------------------------------------------
__global__ __launch_bounds__(512, 2)
void rx_pass2(const float* __restrict__ thetas,
              u64* __restrict__ out, int b0)
{
    extern __shared__ u64 sm2[];             // 8192 u64
    __shared__ u64 c2B[7], s2B[7];

    const int t     = threadIdx.x;
    const int b     = b0 + blockIdx.y;
    const int chunk = blockIdx.x;            // idx bits 6..12

    if (t < 7) {
        float sv, cv;
        sincosf(0.5f * thetas[b * NQ + (6 - t)], &sv, &cv);
        c2B[t] = pk2(cv, cv);
        s2B[t] = pk2(sv, -sv);
    }

    u64* pg = out + ((size_t)b << 20) + ((size_t)chunk << 6);
    const int c  = t & 63;
    const int h0 = t >> 6;                   // 0..7

    u64 amp[16];

    // ---- Round A: h = j | (h0<<4) ; 512B-per-warp coalesced b64 loads ----
    #pragma unroll
    for (int j = 0; j < 16; j++) {
        int h = j | (h0 << 4);
        amp[j] = (u64)__ldcs((const long long*)(pg + (((size_t)h << 13) + c)));
    }
    __syncthreads();   // c2B/s2B visible

    #pragma unroll
    for (int m = 0; m < 4; m++) {
        const u64 c2 = c2B[m], s2 = s2B[m];
        const int st = 1 << m;
        #pragma unroll
        for (int j = 0; j < 16; j++)
            if (!(j & st)) bfly2(amp[j], amp[j | st], c2, s2);
    }
    #pragma unroll
    for (int j = 0; j < 16; j++) {
        int h = j | (h0 << 4);
        sm2[(h << 6) + c] = amp[j];
    }
    __syncthreads();

    // ---- Round B: h = h0 | (j<<3) ----
    #pragma unroll
    for (int j = 0; j < 16; j++) {
        int h = h0 | (j << 3);
        amp[j] = sm2[(h << 6) + c];
    }
    #pragma unroll
    for (int m = 4; m < 7; m++) {
        const u64 c2 = c2B[m], s2 = s2B[m];
        const int st = 1 << (m - 3);
        #pragma unroll
        for (int j = 0; j < 16; j++)
            if (!(j & st)) bfly2(amp[j], amp[j | st], c2, s2);
    }
    // ---- final store: streaming (evict-first) ----
    #pragma unroll
    for (int j = 0; j < 16; j++) {
        int h = h0 | (j << 3);
        __stcs((long long*)(pg + (((size_t)h << 13) + c)), (long long)amp[j]);
    }
}

extern "C" void kernel_launch(void* const* d_in, const int* in_sizes, int n_in,
                              void* d_out, int out_size)
{
    const float* phi    = (const float*)d_in[0];   // [16, 2^20] float32
    const float* thetas = (const float*)d_in[1];   // [16, 20]   float32
    u64* out = (u64*)d_out;                        // [16, 2^20] packed (re,im)

    const int SM1 = 8704 * (int)sizeof(u64);       // 69632 B
    const int SM2 = 8192 * (int)sizeof(u64);       // 65536 B
    cudaFuncSetAttribute(rx_pass1, cudaFuncAttributeMaxDynamicSharedMemorySize, SM1);
    cudaFuncSetAttribute(rx_pass2, cudaFuncAttributeMaxDynamicSharedMemorySize, SM2);

    // Host-side stream/event resources: EXACT round-7 config (2 streams,
    // 3 events) — proven teardown-clean.
    static cudaStream_t s[2] = {nullptr, nullptr};
    static cudaEvent_t eRoot = nullptr, eDone[2] = {nullptr, nullptr};
    if (!s[0]) {
        cudaStreamCreateWithFlags(&s[0], cudaStreamNonBlocking);
        cudaStreamCreateWithFlags(&s[1], cudaStreamNonBlocking);
        cudaEventCreateWithFlags(&eRoot,    cudaEventDisableTiming);
        cudaEventCreateWithFlags(&eDone[0], cudaEventDisableTiming);
        cudaEventCreateWithFlags(&eDone[1], cudaEventDisableTiming);
    }

    // Fork both worker streams off the (capturing) launch stream.
    cudaEventRecord(eRoot, 0);
    cudaStreamWaitEvent(s[0], eRoot, 0);
    cudaStreamWaitEvent(s[1], eRoot, 0);

    // 2 groups of 8 batches, one per stream: only 4 kernels total (fixed
    // per-kernel overhead amortized over the biggest proven bodies).
    for (int g = 0; g < 2; g++) {
        cudaStream_t st = s[g];
        dim3 grid(128, 8);
        rx_pass1<<<grid, 512, SM1, st>>>(phi, thetas, out, g * 8);
        rx_pass2<<<grid, 512, SM2, st>>>(thetas, out, g * 8);
    }

    // Join back into the launch stream.
    cudaEventRecord(eDone[0], s[0]);
    cudaEventRecord(eDone[1], s[1]);
    cudaStreamWaitEvent(0, eDone[0], 0);
    cudaStreamWaitEvent(0, eDone[1], 0);
}